// round 14
// baseline (speedup 1.0000x reference)
#include <cuda_runtime.h>
#include <cuda_fp16.h>
#include <cstdint>

#define SDIM 512
#define FDIM 1024
#define KDIM 1024
#define MDIM 32768          // 64*512

// ---------------- device scratch ----------------
__device__ __half g_xh[(size_t)MDIM * KDIM];   // 64 MB
__device__ __half g_wh[(size_t)FDIM * KDIM];   // 2 MB
__device__ float  g_carry[64 * 4 * FDIM];      // carry h after chunk c, [b][c][f]
__device__ int    g_flag[64 * 4 * 8];          // published flags [b][c][ntile]

// ---------------- merged prep: convert x (16 floats/thread) + W + reset ----------------
__device__ __forceinline__ uint4 pack8(float4 a, float4 b) {
    __half2 h0 = __floats2half2_rn(a.x, a.y);
    __half2 h1 = __floats2half2_rn(a.z, a.w);
    __half2 h2 = __floats2half2_rn(b.x, b.y);
    __half2 h3 = __floats2half2_rn(b.z, b.w);
    uint4 u;
    u.x = *reinterpret_cast<unsigned*>(&h0);
    u.y = *reinterpret_cast<unsigned*>(&h1);
    u.z = *reinterpret_cast<unsigned*>(&h2);
    u.w = *reinterpret_cast<unsigned*>(&h3);
    return u;
}

__global__ __launch_bounds__(256) void prep_kernel(const float* __restrict__ x,
                                                   const float* __restrict__ W) {
    const int bid = blockIdx.x;
    if (bid < 8192) {                       // convert x: 16 floats per thread
        size_t i = ((size_t)bid * 256 + threadIdx.x) * 16;
        float4 a0 = *reinterpret_cast<const float4*>(x + i);
        float4 a1 = *reinterpret_cast<const float4*>(x + i + 4);
        float4 a2 = *reinterpret_cast<const float4*>(x + i + 8);
        float4 a3 = *reinterpret_cast<const float4*>(x + i + 12);
        *reinterpret_cast<uint4*>(g_xh + i)     = pack8(a0, a1);
        *reinterpret_cast<uint4*>(g_xh + i + 8) = pack8(a2, a3);
    } else if (bid < 8448) {                // convert W: 16 floats per thread
        size_t i = ((size_t)(bid - 8192) * 256 + threadIdx.x) * 16;
        float4 a0 = *reinterpret_cast<const float4*>(W + i);
        float4 a1 = *reinterpret_cast<const float4*>(W + i + 4);
        float4 a2 = *reinterpret_cast<const float4*>(W + i + 8);
        float4 a3 = *reinterpret_cast<const float4*>(W + i + 12);
        *reinterpret_cast<uint4*>(g_wh + i)     = pack8(a0, a1);
        *reinterpret_cast<uint4*>(g_wh + i + 8) = pack8(a2, a3);
    } else {                                // reset flags
        for (int i = threadIdx.x; i < 64 * 4 * 8; i += 256) g_flag[i] = 0;
    }
    // PDL: signal the dependent GEMM launch as CTAs complete
    cudaTriggerProgrammaticLaunchCompletion();
}

// ---------------- PTX helpers ----------------
__device__ __forceinline__ void cp_async16(void* smem, const void* gmem) {
    unsigned saddr = (unsigned)__cvta_generic_to_shared(smem);
    asm volatile("cp.async.cg.shared.global [%0], [%1], 16;\n" :: "r"(saddr), "l"(gmem));
}
__device__ __forceinline__ void cp_async_arrive(uint32_t mbar) {
    asm volatile("cp.async.mbarrier.arrive.noinc.shared.b64 [%0];" :: "r"(mbar) : "memory");
}
__device__ __forceinline__ void mbar_init(uint32_t a, uint32_t cnt) {
    asm volatile("mbarrier.init.shared.b64 [%0], %1;" :: "r"(a), "r"(cnt) : "memory");
}
__device__ __forceinline__ void mbar_arrive(uint32_t a) {
    asm volatile("mbarrier.arrive.shared.b64 _, [%0];" :: "r"(a) : "memory");
}
__device__ __forceinline__ void mbar_wait(uint32_t a, uint32_t parity) {
    asm volatile(
        "{\n\t.reg .pred P;\n\t"
        "W%=:\n\tmbarrier.try_wait.parity.shared.b64 P, [%0], %1;\n\t"
        "@P bra D%=;\n\tbra W%=;\n\tD%=:\n\t}"
        :: "r"(a), "r"(parity) : "memory");
}

#define LDSM_X4(r0, r1, r2, r3, addr) \
    asm volatile("ldmatrix.sync.aligned.m8n8.x4.shared.b16 {%0,%1,%2,%3}, [%4];" \
                 : "=r"(r0), "=r"(r1), "=r"(r2), "=r"(r3) : "r"(addr))

__device__ __forceinline__ int ld_acquire(const int* p) {
    int v;
    asm volatile("ld.acquire.gpu.global.b32 %0, [%1];" : "=r"(v) : "l"(p) : "memory");
    return v;
}
__device__ __forceinline__ void st_release(int* p, int v) {
    asm volatile("st.release.gpu.global.b32 [%0], %1;" :: "l"(p), "r"(v) : "memory");
}

// ---------------- fused fp16 GEMM + EMA scan, mbarrier pipeline ----------------
// CTA 128x128, BK=64, 3 stages, 8 warps (2M x 4N), warp tile 64x32, 2 CTA/SM.
#define BM 128
#define BN 128
#define BK 64
#define ROW_B 144                       // 64 halves + 16B pad
#define TILE_B (128 * ROW_B)            // 18432
#define STAGE_B (2 * TILE_B)            // 36864
#define STAGES 3
#define MBAR_OFF (STAGES * STAGE_B)     // 110592
#define GEMM_SMEM (MBAR_OFF + 64)       // 110656
#define EPI_STRIDE 129

__global__ __launch_bounds__(256, 2) void gemm_fused_kernel(
    float* __restrict__ hid, float* __restrict__ hk)
{
    extern __shared__ char smem[];
    const uint32_t smem_base = (uint32_t)__cvta_generic_to_shared(smem);
    const uint32_t mb_full  = smem_base + MBAR_OFF;        // +0,8,16
    const uint32_t mb_empty = smem_base + MBAR_OFF + 24;   // +0,8,16

    const int tid   = threadIdx.x;
    const int lane  = tid & 31;
    const int warp  = tid >> 5;
    const int warpM = warp >> 2;   // 0..1 (64 rows)
    const int warpN = warp & 3;    // 0..3 (32 cols)

    const int ntile = blockIdx.x;          // 0..7
    const int b     = blockIdx.y & 63;     // batch
    const int c     = blockIdx.y >> 6;     // s-chunk (outermost)
    const int m0    = (b * 4 + c) * BM;
    const int n0    = ntile * BN;

    if (tid == 0) {
        #pragma unroll
        for (int s = 0; s < STAGES; s++) {
            mbar_init(mb_full + s * 8, 256);
            mbar_init(mb_empty + s * 8, 8);
        }
    }
    __syncthreads();

    // PDL: wait for prep_kernel's results (g_xh, g_wh, g_flag) to be visible.
    // Launch setup + mbarrier init above overlap the prep tail.
    cudaGridDependencySynchronize();

    float acc[4][4][4];
    #pragma unroll
    for (int i = 0; i < 4; i++)
        #pragma unroll
        for (int j = 0; j < 4; j++)
            #pragma unroll
            for (int k = 0; k < 4; k++)
                acc[i][j][k] = 0.0f;

    const int ld_row = tid >> 3;
    const int ld_c   = tid & 7;

    auto load_A_chunk = [&](int slot, int k0, int i) {
        char* sa = smem + slot * STAGE_B;
        int row = ld_row + i * 32;
        cp_async16(sa + row * ROW_B + ld_c * 16,
                   g_xh + (size_t)(m0 + row) * KDIM + k0 + ld_c * 8);
    };
    auto load_B_chunk = [&](int slot, int k0, int i) {
        char* sb = smem + slot * STAGE_B + TILE_B;
        int row = ld_row + i * 32;
        cp_async16(sb + row * ROW_B + ld_c * 16,
                   g_wh + (size_t)(n0 + row) * KDIM + k0 + ld_c * 8);
    };

    // prologue: stages 0 and 1
    #pragma unroll
    for (int i = 0; i < 4; i++) load_A_chunk(0, 0, i);
    #pragma unroll
    for (int i = 0; i < 4; i++) load_B_chunk(0, 0, i);
    cp_async_arrive(mb_full + 0 * 8);
    #pragma unroll
    for (int i = 0; i < 4; i++) load_A_chunk(1, BK, i);
    #pragma unroll
    for (int i = 0; i < 4; i++) load_B_chunk(1, BK, i);
    cp_async_arrive(mb_full + 1 * 8);

    const int a_row = warpM * 64 + (lane & 15);
    const int a_kc  = (lane >> 4) << 3;
    const int b_row = warpN * 32 + (lane & 7) + ((lane >> 4) << 3);
    const int b_kc  = ((lane >> 3) & 1) << 3;

    auto do_kk = [&](uint32_t sa, uint32_t sb, int kb) {
        uint32_t bb[2][4];
        #pragma unroll
        for (int p = 0; p < 2; p++) {
            uint32_t addr = sb + (b_row + p * 16) * ROW_B + (kb + b_kc) * 2;
            LDSM_X4(bb[p][0], bb[p][1], bb[p][2], bb[p][3], addr);
        }
        #pragma unroll
        for (int mt = 0; mt < 4; mt++) {
            uint32_t a0, a1, a2, a3;
            uint32_t addr = sa + (a_row + mt * 16) * ROW_B + (kb + a_kc) * 2;
            LDSM_X4(a0, a1, a2, a3, addr);
            #pragma unroll
            for (int p = 0; p < 2; p++) {
                asm volatile(
                    "mma.sync.aligned.m16n8k16.row.col.f32.f16.f16.f32 "
                    "{%0,%1,%2,%3}, {%4,%5,%6,%7}, {%8,%9}, {%0,%1,%2,%3};\n"
                    : "+f"(acc[mt][2*p][0]), "+f"(acc[mt][2*p][1]),
                      "+f"(acc[mt][2*p][2]), "+f"(acc[mt][2*p][3])
                    : "r"(a0), "r"(a1), "r"(a2), "r"(a3),
                      "r"(bb[p][0]), "r"(bb[p][1]));
                asm volatile(
                    "mma.sync.aligned.m16n8k16.row.col.f32.f16.f16.f32 "
                    "{%0,%1,%2,%3}, {%4,%5,%6,%7}, {%8,%9}, {%0,%1,%2,%3};\n"
                    : "+f"(acc[mt][2*p+1][0]), "+f"(acc[mt][2*p+1][1]),
                      "+f"(acc[mt][2*p+1][2]), "+f"(acc[mt][2*p+1][3])
                    : "r"(a0), "r"(a1), "r"(a2), "r"(a3),
                      "r"(bb[p][2]), "r"(bb[p][3]));
            }
        }
    };

    const int KTILES = KDIM / BK;   // 16
    #pragma unroll 1
    for (int kt = 0; kt < KTILES; kt++) {
        const int slot = kt % STAGES;
        mbar_wait(mb_full + slot * 8, (kt / 3) & 1);

        const uint32_t sa = smem_base + slot * STAGE_B;
        const uint32_t sb = sa + TILE_B;
        const int G  = kt + 2;
        const bool dl = G < KTILES;
        const int gs = G % STAGES;
        const int k0 = G * BK;

        do_kk(sa, sb, 0);
        if (dl) {
            if (G >= 3) mbar_wait(mb_empty + gs * 8, ((G / 3) - 1) & 1);
            load_A_chunk(gs, k0, 0); load_A_chunk(gs, k0, 1);
        }
        do_kk(sa, sb, 16);
        if (dl) { load_A_chunk(gs, k0, 2); load_A_chunk(gs, k0, 3); }
        do_kk(sa, sb, 32);
        if (dl) { load_B_chunk(gs, k0, 0); load_B_chunk(gs, k0, 1); }
        do_kk(sa, sb, 48);
        if (dl) {
            load_B_chunk(gs, k0, 2); load_B_chunk(gs, k0, 3);
            cp_async_arrive(mb_full + gs * 8);
        }
        if (lane == 0) mbar_arrive(mb_empty + slot * 8);
    }
    __syncthreads();

    // ---------------- fused epilogue: stage C tile, even/odd split scan ----------------
    float* ctile = reinterpret_cast<float*>(smem);   // [128][EPI_STRIDE]

    #pragma unroll
    for (int mt = 0; mt < 4; mt++) {
        #pragma unroll
        for (int nt = 0; nt < 4; nt++) {
            int r  = warpM * 64 + mt * 16 + (lane >> 2);
            int cc = warpN * 32 + nt * 8 + (lane & 3) * 2;
            ctile[r * EPI_STRIDE + cc]           = acc[mt][nt][0];
            ctile[r * EPI_STRIDE + cc + 1]       = acc[mt][nt][1];
            ctile[(r + 8) * EPI_STRIDE + cc]     = acc[mt][nt][2];
            ctile[(r + 8) * EPI_STRIDE + cc + 1] = acc[mt][nt][3];
        }
    }

    if (c > 0 && tid == 0) {
        const int* flag = &g_flag[(b * 4 + (c - 1)) * 8 + ntile];
        while (ld_acquire(flag) == 0) { }
    }
    __syncthreads();

    {
        const int f    = tid & 127;
        const int half = tid >> 7;          // 0: even s, 1: odd s
        const int fg   = n0 + f;
        const float hp = (c > 0) ? g_carry[(b * 4 + (c - 1)) * FDIM + fg] : 0.0f;
        float* orow = hid + (size_t)(b * SDIM + c * 128) * FDIM + fg;
        float h;
        if (half == 0) {
            h = 0.5f * (hp + ctile[f]);                       // s=0
            __stcs(orow, h);
            #pragma unroll 4
            for (int k = 1; k < 64; k++) {
                float y1 = ctile[(2 * k - 1) * EPI_STRIDE + f];
                float y2 = ctile[(2 * k) * EPI_STRIDE + f];
                h = 0.25f * h + (0.25f * y1 + 0.5f * y2);
                __stcs(orow + (size_t)(2 * k) * FDIM, h);
            }
        } else {
            float y0 = ctile[f];
            float y1 = ctile[EPI_STRIDE + f];
            h = 0.25f * hp + 0.25f * y0 + 0.5f * y1;          // s=1
            __stcs(orow + FDIM, h);
            #pragma unroll 4
            for (int k = 1; k < 64; k++) {
                float ya = ctile[(2 * k) * EPI_STRIDE + f];
                float yb = ctile[(2 * k + 1) * EPI_STRIDE + f];
                h = 0.25f * h + (0.25f * ya + 0.5f * yb);
                __stcs(orow + (size_t)(2 * k + 1) * FDIM, h);
            }
            if (c < 3) g_carry[(b * 4 + c) * FDIM + fg] = h;
            else       hk[b * FDIM + fg] = h;
        }
    }
    __syncthreads();
    if (tid == 0 && c < 3) {
        __threadfence();
        st_release(&g_flag[(b * 4 + c) * 8 + ntile], 1);
    }
}

extern "C" void kernel_launch(void* const* d_in, const int* in_sizes, int n_in,
                              void* d_out, int out_size) {
    const float* x = (const float*)d_in[0];   // [64, 512, 1024]
    const float* W = (const float*)d_in[1];   // [1024, 1024]
    float* out = (float*)d_out;
    float* hk  = out;                          // [64, 1024]
    float* hid = out + (size_t)64 * FDIM;      // [64, 512, 1024]

    cudaFuncSetAttribute(gemm_fused_kernel,
                         cudaFuncAttributeMaxDynamicSharedMemorySize, GEMM_SMEM);

    prep_kernel<<<8449, 256>>>(x, W);

    // PDL launch: GEMM starts while prep drains; device-side
    // cudaGridDependencySynchronize() enforces the data dependency.
    cudaLaunchConfig_t cfg = {};
    cfg.gridDim  = dim3(FDIM / BN, 256);       // (8, 256); y = c*64 + b
    cfg.blockDim = dim3(256, 1, 1);
    cfg.dynamicSmemBytes = GEMM_SMEM;
    cfg.stream = 0;
    cudaLaunchAttribute attr[1];
    attr[0].id = cudaLaunchAttributeProgrammaticStreamSerialization;
    attr[0].val.programmaticStreamSerializationAllowed = 1;
    cfg.attrs = attr;
    cfg.numAttrs = 1;
    cudaLaunchKernelEx(&cfg, gemm_fused_kernel, hid, hk);
}

// round 15
// speedup vs baseline: 1.0632x; 1.0632x over previous
#include <cuda_runtime.h>
#include <cuda_fp16.h>
#include <cstdint>

#define SDIM 512
#define FDIM 1024
#define KDIM 1024
#define MDIM 32768          // 64*512

// ---------------- device scratch ----------------
__device__ __half g_xh[(size_t)MDIM * KDIM];   // 64 MB
__device__ __half g_wh[(size_t)FDIM * KDIM];   // 2 MB
__device__ float  g_carry[64 * 4 * FDIM];      // carry h after chunk c, [b][c][f]
__device__ int    g_flag[64 * 4 * 8];          // published flags [b][c][ntile]

// ---------------- merged prep: convert x (16 floats/thread) + W + reset ----------------
__device__ __forceinline__ uint4 pack8(float4 a, float4 b) {
    __half2 h0 = __floats2half2_rn(a.x, a.y);
    __half2 h1 = __floats2half2_rn(a.z, a.w);
    __half2 h2 = __floats2half2_rn(b.x, b.y);
    __half2 h3 = __floats2half2_rn(b.z, b.w);
    uint4 u;
    u.x = *reinterpret_cast<unsigned*>(&h0);
    u.y = *reinterpret_cast<unsigned*>(&h1);
    u.z = *reinterpret_cast<unsigned*>(&h2);
    u.w = *reinterpret_cast<unsigned*>(&h3);
    return u;
}

__global__ __launch_bounds__(256) void prep_kernel(const float* __restrict__ x,
                                                   const float* __restrict__ W) {
    const int bid = blockIdx.x;
    if (bid < 8192) {                       // convert x: 16 floats per thread
        size_t i = ((size_t)bid * 256 + threadIdx.x) * 16;
        float4 a0 = *reinterpret_cast<const float4*>(x + i);
        float4 a1 = *reinterpret_cast<const float4*>(x + i + 4);
        float4 a2 = *reinterpret_cast<const float4*>(x + i + 8);
        float4 a3 = *reinterpret_cast<const float4*>(x + i + 12);
        *reinterpret_cast<uint4*>(g_xh + i)     = pack8(a0, a1);
        *reinterpret_cast<uint4*>(g_xh + i + 8) = pack8(a2, a3);
    } else if (bid < 8448) {                // convert W: 16 floats per thread
        size_t i = ((size_t)(bid - 8192) * 256 + threadIdx.x) * 16;
        float4 a0 = *reinterpret_cast<const float4*>(W + i);
        float4 a1 = *reinterpret_cast<const float4*>(W + i + 4);
        float4 a2 = *reinterpret_cast<const float4*>(W + i + 8);
        float4 a3 = *reinterpret_cast<const float4*>(W + i + 12);
        *reinterpret_cast<uint4*>(g_wh + i)     = pack8(a0, a1);
        *reinterpret_cast<uint4*>(g_wh + i + 8) = pack8(a2, a3);
    } else {                                // reset flags
        for (int i = threadIdx.x; i < 64 * 4 * 8; i += 256) g_flag[i] = 0;
    }
}

// ---------------- PTX helpers ----------------
__device__ __forceinline__ void cp_async16(void* smem, const void* gmem) {
    unsigned saddr = (unsigned)__cvta_generic_to_shared(smem);
    asm volatile("cp.async.cg.shared.global [%0], [%1], 16;\n" :: "r"(saddr), "l"(gmem));
}
__device__ __forceinline__ void cp_async_arrive(uint32_t mbar) {
    asm volatile("cp.async.mbarrier.arrive.noinc.shared.b64 [%0];" :: "r"(mbar) : "memory");
}
__device__ __forceinline__ void mbar_init(uint32_t a, uint32_t cnt) {
    asm volatile("mbarrier.init.shared.b64 [%0], %1;" :: "r"(a), "r"(cnt) : "memory");
}
__device__ __forceinline__ void mbar_arrive(uint32_t a) {
    asm volatile("mbarrier.arrive.shared.b64 _, [%0];" :: "r"(a) : "memory");
}
__device__ __forceinline__ void mbar_wait(uint32_t a, uint32_t parity) {
    asm volatile(
        "{\n\t.reg .pred P;\n\t"
        "W%=:\n\tmbarrier.try_wait.parity.shared.b64 P, [%0], %1;\n\t"
        "@P bra D%=;\n\tbra W%=;\n\tD%=:\n\t}"
        :: "r"(a), "r"(parity) : "memory");
}

#define LDSM_X4(r0, r1, r2, r3, addr) \
    asm volatile("ldmatrix.sync.aligned.m8n8.x4.shared.b16 {%0,%1,%2,%3}, [%4];" \
                 : "=r"(r0), "=r"(r1), "=r"(r2), "=r"(r3) : "r"(addr))

__device__ __forceinline__ int ld_acquire(const int* p) {
    int v;
    asm volatile("ld.acquire.gpu.global.b32 %0, [%1];" : "=r"(v) : "l"(p) : "memory");
    return v;
}
__device__ __forceinline__ void st_release(int* p, int v) {
    asm volatile("st.release.gpu.global.b32 [%0], %1;" :: "l"(p), "r"(v) : "memory");
}

// ---------------- fused fp16 GEMM + EMA scan, mbarrier pipeline ----------------
// CTA 128x128, BK=64, 3 stages, 8 warps (2M x 4N), warp tile 64x32, 2 CTA/SM.
#define BM 128
#define BN 128
#define BK 64
#define ROW_B 144                       // 64 halves + 16B pad
#define TILE_B (128 * ROW_B)            // 18432
#define STAGE_B (2 * TILE_B)            // 36864
#define STAGES 3
#define MBAR_OFF (STAGES * STAGE_B)     // 110592
#define GEMM_SMEM (MBAR_OFF + 64)       // 110656
#define EPI_STRIDE_H 136                // halves per ctile row (272B, conflict-free STS)

__global__ __launch_bounds__(256, 2) void gemm_fused_kernel(
    float* __restrict__ hid, float* __restrict__ hk)
{
    extern __shared__ char smem[];
    const uint32_t smem_base = (uint32_t)__cvta_generic_to_shared(smem);
    const uint32_t mb_full  = smem_base + MBAR_OFF;        // +0,8,16
    const uint32_t mb_empty = smem_base + MBAR_OFF + 24;   // +0,8,16

    const int tid   = threadIdx.x;
    const int lane  = tid & 31;
    const int warp  = tid >> 5;
    const int warpM = warp >> 2;   // 0..1 (64 rows)
    const int warpN = warp & 3;    // 0..3 (32 cols)

    const int ntile = blockIdx.x;          // 0..7
    const int b     = blockIdx.y & 63;     // batch
    const int c     = blockIdx.y >> 6;     // s-chunk (outermost)
    const int m0    = (b * 4 + c) * BM;
    const int n0    = ntile * BN;

    if (tid == 0) {
        #pragma unroll
        for (int s = 0; s < STAGES; s++) {
            mbar_init(mb_full + s * 8, 256);
            mbar_init(mb_empty + s * 8, 8);
        }
    }
    __syncthreads();

    float acc[4][4][4];
    #pragma unroll
    for (int i = 0; i < 4; i++)
        #pragma unroll
        for (int j = 0; j < 4; j++)
            #pragma unroll
            for (int k = 0; k < 4; k++)
                acc[i][j][k] = 0.0f;

    const int ld_row = tid >> 3;
    const int ld_c   = tid & 7;

    auto load_A_chunk = [&](int slot, int k0, int i) {
        char* sa = smem + slot * STAGE_B;
        int row = ld_row + i * 32;
        cp_async16(sa + row * ROW_B + ld_c * 16,
                   g_xh + (size_t)(m0 + row) * KDIM + k0 + ld_c * 8);
    };
    auto load_B_chunk = [&](int slot, int k0, int i) {
        char* sb = smem + slot * STAGE_B + TILE_B;
        int row = ld_row + i * 32;
        cp_async16(sb + row * ROW_B + ld_c * 16,
                   g_wh + (size_t)(n0 + row) * KDIM + k0 + ld_c * 8);
    };

    // prologue: stages 0 and 1
    #pragma unroll
    for (int i = 0; i < 4; i++) load_A_chunk(0, 0, i);
    #pragma unroll
    for (int i = 0; i < 4; i++) load_B_chunk(0, 0, i);
    cp_async_arrive(mb_full + 0 * 8);
    #pragma unroll
    for (int i = 0; i < 4; i++) load_A_chunk(1, BK, i);
    #pragma unroll
    for (int i = 0; i < 4; i++) load_B_chunk(1, BK, i);
    cp_async_arrive(mb_full + 1 * 8);

    const int a_row = warpM * 64 + (lane & 15);
    const int a_kc  = (lane >> 4) << 3;
    const int b_row = warpN * 32 + (lane & 7) + ((lane >> 4) << 3);
    const int b_kc  = ((lane >> 3) & 1) << 3;

    auto do_kk = [&](uint32_t sa, uint32_t sb, int kb) {
        uint32_t bb[2][4];
        #pragma unroll
        for (int p = 0; p < 2; p++) {
            uint32_t addr = sb + (b_row + p * 16) * ROW_B + (kb + b_kc) * 2;
            LDSM_X4(bb[p][0], bb[p][1], bb[p][2], bb[p][3], addr);
        }
        #pragma unroll
        for (int mt = 0; mt < 4; mt++) {
            uint32_t a0, a1, a2, a3;
            uint32_t addr = sa + (a_row + mt * 16) * ROW_B + (kb + a_kc) * 2;
            LDSM_X4(a0, a1, a2, a3, addr);
            #pragma unroll
            for (int p = 0; p < 2; p++) {
                asm volatile(
                    "mma.sync.aligned.m16n8k16.row.col.f32.f16.f16.f32 "
                    "{%0,%1,%2,%3}, {%4,%5,%6,%7}, {%8,%9}, {%0,%1,%2,%3};\n"
                    : "+f"(acc[mt][2*p][0]), "+f"(acc[mt][2*p][1]),
                      "+f"(acc[mt][2*p][2]), "+f"(acc[mt][2*p][3])
                    : "r"(a0), "r"(a1), "r"(a2), "r"(a3),
                      "r"(bb[p][0]), "r"(bb[p][1]));
                asm volatile(
                    "mma.sync.aligned.m16n8k16.row.col.f32.f16.f16.f32 "
                    "{%0,%1,%2,%3}, {%4,%5,%6,%7}, {%8,%9}, {%0,%1,%2,%3};\n"
                    : "+f"(acc[mt][2*p+1][0]), "+f"(acc[mt][2*p+1][1]),
                      "+f"(acc[mt][2*p+1][2]), "+f"(acc[mt][2*p+1][3])
                    : "r"(a0), "r"(a1), "r"(a2), "r"(a3),
                      "r"(bb[p][2]), "r"(bb[p][3]));
            }
        }
    };

    const int KTILES = KDIM / BK;   // 16
    #pragma unroll 1
    for (int kt = 0; kt < KTILES; kt++) {
        const int slot = kt % STAGES;
        mbar_wait(mb_full + slot * 8, (kt / 3) & 1);

        const uint32_t sa = smem_base + slot * STAGE_B;
        const uint32_t sb = sa + TILE_B;
        const int G  = kt + 2;
        const bool dl = G < KTILES;
        const int gs = G % STAGES;
        const int k0 = G * BK;

        do_kk(sa, sb, 0);
        if (dl) {
            if (G >= 3) mbar_wait(mb_empty + gs * 8, ((G / 3) - 1) & 1);
            load_A_chunk(gs, k0, 0); load_A_chunk(gs, k0, 1);
        }
        do_kk(sa, sb, 16);
        if (dl) { load_A_chunk(gs, k0, 2); load_A_chunk(gs, k0, 3); }
        do_kk(sa, sb, 32);
        if (dl) { load_B_chunk(gs, k0, 0); load_B_chunk(gs, k0, 1); }
        do_kk(sa, sb, 48);
        if (dl) {
            load_B_chunk(gs, k0, 2); load_B_chunk(gs, k0, 3);
            cp_async_arrive(mb_full + gs * 8);
        }
        if (lane == 0) mbar_arrive(mb_empty + slot * 8);
    }
    __syncthreads();

    // ---------------- fused epilogue: fp16 ctile staging, even/odd split scan ----------------
    __half* ctile = reinterpret_cast<__half*>(smem);   // [128][EPI_STRIDE_H], 34.8 KB

    #pragma unroll
    for (int mt = 0; mt < 4; mt++) {
        #pragma unroll
        for (int nt = 0; nt < 4; nt++) {
            int r  = warpM * 64 + mt * 16 + (lane >> 2);
            int cc = warpN * 32 + nt * 8 + (lane & 3) * 2;
            __half2 v0 = __floats2half2_rn(acc[mt][nt][0], acc[mt][nt][1]);
            __half2 v1 = __floats2half2_rn(acc[mt][nt][2], acc[mt][nt][3]);
            *reinterpret_cast<__half2*>(ctile + r * EPI_STRIDE_H + cc)       = v0;
            *reinterpret_cast<__half2*>(ctile + (r + 8) * EPI_STRIDE_H + cc) = v1;
        }
    }

    if (c > 0 && tid == 0) {
        const int* flag = &g_flag[(b * 4 + (c - 1)) * 8 + ntile];
        while (ld_acquire(flag) == 0) { }
    }
    __syncthreads();

    {
        const int f    = tid & 127;
        const int half = tid >> 7;          // 0: even s, 1: odd s
        const int fg   = n0 + f;
        const float hp = (c > 0) ? g_carry[(b * 4 + (c - 1)) * FDIM + fg] : 0.0f;
        float* orow = hid + (size_t)(b * SDIM + c * 128) * FDIM + fg;
        float h;
        if (half == 0) {
            h = 0.5f * (hp + __half2float(ctile[f]));          // s=0
            __stcs(orow, h);
            #pragma unroll 4
            for (int k = 1; k < 64; k++) {
                float y1 = __half2float(ctile[(2 * k - 1) * EPI_STRIDE_H + f]);
                float y2 = __half2float(ctile[(2 * k) * EPI_STRIDE_H + f]);
                h = 0.25f * h + (0.25f * y1 + 0.5f * y2);
                __stcs(orow + (size_t)(2 * k) * FDIM, h);
            }
        } else {
            float y0 = __half2float(ctile[f]);
            float y1 = __half2float(ctile[EPI_STRIDE_H + f]);
            h = 0.25f * hp + 0.25f * y0 + 0.5f * y1;           // s=1
            __stcs(orow + FDIM, h);
            #pragma unroll 4
            for (int k = 1; k < 64; k++) {
                float ya = __half2float(ctile[(2 * k) * EPI_STRIDE_H + f]);
                float yb = __half2float(ctile[(2 * k + 1) * EPI_STRIDE_H + f]);
                h = 0.25f * h + (0.25f * ya + 0.5f * yb);
                __stcs(orow + (size_t)(2 * k + 1) * FDIM, h);
            }
            if (c < 3) g_carry[(b * 4 + c) * FDIM + fg] = h;
            else       hk[b * FDIM + fg] = h;
        }
    }
    __syncthreads();
    if (tid == 0 && c < 3) {
        __threadfence();
        st_release(&g_flag[(b * 4 + c) * 8 + ntile], 1);
    }
}

extern "C" void kernel_launch(void* const* d_in, const int* in_sizes, int n_in,
                              void* d_out, int out_size) {
    const float* x = (const float*)d_in[0];   // [64, 512, 1024]
    const float* W = (const float*)d_in[1];   // [1024, 1024]
    float* out = (float*)d_out;
    float* hk  = out;                          // [64, 1024]
    float* hid = out + (size_t)64 * FDIM;      // [64, 512, 1024]

    cudaFuncSetAttribute(gemm_fused_kernel,
                         cudaFuncAttributeMaxDynamicSharedMemorySize, GEMM_SMEM);

    prep_kernel<<<8449, 256>>>(x, W);
    dim3 grid(FDIM / BN, 256);                 // y = c*64 + b
    gemm_fused_kernel<<<grid, 256, GEMM_SMEM>>>(hid, hk);
}